// round 5
// baseline (speedup 1.0000x reference)
#include <cuda_runtime.h>
#include <cstdint>

// Problem constants
#define BB    128    // batch
#define TT    96     // time
#define HH    64     // hidden = input dim
#define G4    256    // 4*H gates
#define NSCAN 27     // scan 0: fwd prefix (25 steps, collect max)
                     // scans 1..25: suffix scans (96-s steps, final h)
                     // scan 26: reverse prefix (25 steps, collect max)
#define RPW   4      // rows (scan,batch) per warp
#define WPB   6      // warps per block
#define NTHREADS (WPB*32)

// Scratch (static device globals — no allocation)
__device__ __align__(16) float g_xz[BB*TT*G4];     // x@Wih^T + bias, gate-permuted
__device__ __align__(16) float g_hsuf[25*BB*HH];   // final h of suffix scans
__device__ __align__(16) float g_mp[BB*HH];        // running max of forward-prefix h
__device__ __align__(16) float g_mf[BB*HH];        // running max of reverse-prefix h

// ---- packed f32x2 helpers (sm_103a) ----
__device__ __forceinline__ unsigned long long pack_dup(float v) {
    unsigned long long r;
    asm("mov.b64 %0, {%1, %1};" : "=l"(r) : "f"(v));
    return r;
}
__device__ __forceinline__ unsigned long long pack2(float lo, float hi) {
    unsigned long long r;
    asm("mov.b64 %0, {%1, %2};" : "=l"(r) : "f"(lo), "f"(hi));
    return r;
}
__device__ __forceinline__ void unpack2(unsigned long long v, float& lo, float& hi) {
    asm("mov.b64 {%0, %1}, %2;" : "=f"(lo), "=f"(hi) : "l"(v));
}
__device__ __forceinline__ void fma2(unsigned long long& acc, unsigned long long a,
                                     unsigned long long b) {
    asm("fma.rn.f32x2 %0, %1, %2, %0;" : "+l"(acc) : "l"(a), "l"(b));
}
__device__ __forceinline__ unsigned long long add2(unsigned long long a, unsigned long long b) {
    unsigned long long r;
    asm("add.rn.f32x2 %0, %1, %2;" : "=l"(r) : "l"(a), "l"(b));
    return r;
}

// ---- activations (~1e-6 rel err, safely under 1e-3 budget) ----
__device__ __forceinline__ float sigf(float x) {
    return __fdividef(1.0f, 1.0f + __expf(-x));
}
__device__ __forceinline__ float tanh_(float x) {
    return __fdividef(2.0f, 1.0f + __expf(-2.0f*x)) - 1.0f;
}

// Permutation (split-half, bank-conflict-free):
// Each weight/xz row of 256 floats = [ wA half (128) | wB half (128) ].
//   wA half: offset      j*4 + q,  q = 0..3  -> gate q>>1 (i,f), unit 2j+(q&1)
//   wB half: offset 128 + j*4 + q, q = 0..3  -> gate 2+(q>>1) (g,o), unit 2j+(q&1)
// Lane j reads 16B at j*16B stride in each half -> LDS.128 conflict-free.
// h state: hs[u*RPW + r]; units 2*lane (r=0..3) and 2*lane+1 (r=0..3) are two
// contiguous float4 spans -> written as two STS.128 (byte-floor bound, no
// conflict overage), read as one broadcast LDS.128 per k.

// ============================================================================
// Kernel 1: XZ[b][t][col] = bias[col] + sum_k x[b][t][k] * Wih_perm[k][col]
// 12288 rows, RPW rows/warp, 3072 warps -> 512 blocks of 6 warps.
// ============================================================================
__global__ void __launch_bounds__(NTHREADS) k_xz(
    const float* __restrict__ x, const float* __restrict__ Wih,
    const float* __restrict__ bih, const float* __restrict__ bhh)
{
    extern __shared__ __align__(16) float smem[];
    float* wsm = smem;                    // [64][256] permuted Wih (split-half)
    float* xsm = smem + HH*G4;            // [WPB][64][RPW] staged x

    int tid = threadIdx.x;
    for (int d = tid; d < HH*G4; d += NTHREADS) {
        int k = d >> 8, c = d & 255;
        int half = c >> 7, cc = c & 127;
        int j = cc >> 2, q = half*4 + (cc & 3);
        int row = (q >> 1)*64 + 2*j + (q & 1);
        wsm[d] = Wih[row*HH + k];
    }
    __syncthreads();

    int wid  = tid >> 5, lane = tid & 31;
    int gw   = blockIdx.x*WPB + wid;      // 0..3071
    int row0 = gw*RPW;                    // (b*96+t) row index
    float* xs = xsm + wid*(64*RPW);

    // stage x rows into [k][r] packed layout
    #pragma unroll
    for (int r = 0; r < RPW; r++) {
        float2 v = ((const float2*)(x + (row0 + r)*HH))[lane];
        xs[(2*lane    )*RPW + r] = v.x;
        xs[(2*lane + 1)*RPW + r] = v.y;
    }
    __syncwarp();

    // accumulators start at bias
    unsigned long long acc[RPW][4];
    #pragma unroll
    for (int g = 0; g < 4; g++) {
        int u = g*64 + 2*lane;
        unsigned long long bp = pack2(bih[u] + bhh[u], bih[u+1] + bhh[u+1]);
        #pragma unroll
        for (int r = 0; r < RPW; r++) acc[r][g] = bp;
    }

    const float* wrow = wsm + lane*4;     // 16B lane stride (conflict-free)
    #pragma unroll 8
    for (int k = 0; k < 64; k++) {
        ulonglong2 wA = *(const ulonglong2*)(wrow + k*G4);
        ulonglong2 wB = *(const ulonglong2*)(wrow + k*G4 + 128);
        float4 xk = *(const float4*)(xs + k*RPW);
        unsigned long long xd0 = pack_dup(xk.x), xd1 = pack_dup(xk.y);
        unsigned long long xd2 = pack_dup(xk.z), xd3 = pack_dup(xk.w);
        fma2(acc[0][0], wA.x, xd0); fma2(acc[0][1], wA.y, xd0);
        fma2(acc[0][2], wB.x, xd0); fma2(acc[0][3], wB.y, xd0);
        fma2(acc[1][0], wA.x, xd1); fma2(acc[1][1], wA.y, xd1);
        fma2(acc[1][2], wB.x, xd1); fma2(acc[1][3], wB.y, xd1);
        fma2(acc[2][0], wA.x, xd2); fma2(acc[2][1], wA.y, xd2);
        fma2(acc[2][2], wB.x, xd2); fma2(acc[2][3], wB.y, xd2);
        fma2(acc[3][0], wA.x, xd3); fma2(acc[3][1], wA.y, xd3);
        fma2(acc[3][2], wB.x, xd3); fma2(acc[3][3], wB.y, xd3);
    }

    #pragma unroll
    for (int r = 0; r < RPW; r++) {
        float* base = g_xz + (row0 + r)*G4;
        *(ulonglong2*)(base + lane*4)       = make_ulonglong2(acc[r][0], acc[r][1]);
        *(ulonglong2*)(base + 128 + lane*4) = make_ulonglong2(acc[r][2], acc[r][3]);
    }
}

// ============================================================================
// Kernel 2: the 27 LSTM scans. 864 warps (27 scans x 32 warps x 4 batch rows),
// 144 blocks of 6 warps (~one wave). Whh permuted in smem; h in smem [k][r].
// ============================================================================
__global__ void __launch_bounds__(NTHREADS) k_rec(const float* __restrict__ Whh)
{
    extern __shared__ __align__(16) float smem[];
    float* wsm    = smem;                 // [64][256] permuted Whh (split-half)
    float* hsmall = smem + HH*G4;         // [WPB][64][RPW] h state

    int tid = threadIdx.x;
    for (int d = tid; d < HH*G4; d += NTHREADS) {
        int k = d >> 8, c = d & 255;
        int half = c >> 7, cc = c & 127;
        int j = cc >> 2, q = half*4 + (cc & 3);
        int row = (q >> 1)*64 + 2*j + (q & 1);
        wsm[d] = Whh[row*HH + k];
    }
    int wid = tid >> 5, lane = tid & 31;
    float* hs = hsmall + wid*(64*RPW);
    #pragma unroll
    for (int i = 0; i < 8; i++) hs[lane + 32*i] = 0.0f;
    __syncthreads();

    int gw = blockIdx.x*WPB + wid;        // 0..863
    int s  = gw % NSCAN;                  // interleave scans for load balance
    int b0 = (gw / NSCAN) * RPW;

    int tt, tstep, nsteps;
    if (s == 0)            { tt = 0;  tstep = 1;  nsteps = 25; }
    else if (s == NSCAN-1) { tt = 95; tstep = -1; nsteps = 25; }
    else                   { tt = s;  tstep = 1;  nsteps = 96 - s; }
    const bool collect = (s == 0) || (s == NSCAN-1);

    float c0[RPW], c1[RPW], m0[RPW], m1[RPW], hh0[RPW], hh1[RPW];
    #pragma unroll
    for (int r = 0; r < RPW; r++) {
        c0[r] = c1[r] = 0.0f; hh0[r] = hh1[r] = 0.0f;
        m0[r] = m1[r] = -1e30f;
    }

    const float* wrow = wsm + lane*4;     // 16B lane stride (conflict-free)

    for (int step = 0; step < nsteps; step++, tt += tstep) {
        // prefetch XZ (L2) — consumed after the k-loop, latency fully hidden
        ulonglong2 xz0[RPW], xz1[RPW];
        #pragma unroll
        for (int r = 0; r < RPW; r++) {
            const float* base = g_xz + ((b0 + r)*TT + tt)*G4;
            xz0[r] = *(const ulonglong2*)(base + lane*4);
            xz1[r] = *(const ulonglong2*)(base + 128 + lane*4);
        }

        unsigned long long a[RPW][4];
        #pragma unroll
        for (int r = 0; r < RPW; r++)
            a[r][0] = a[r][1] = a[r][2] = a[r][3] = 0ull;

        #pragma unroll 8
        for (int k = 0; k < 64; k++) {
            ulonglong2 wA = *(const ulonglong2*)(wrow + k*G4);
            ulonglong2 wB = *(const ulonglong2*)(wrow + k*G4 + 128);
            float4 hk = *(const float4*)(hs + k*RPW);   // broadcast, conflict-free
            unsigned long long hd0 = pack_dup(hk.x), hd1 = pack_dup(hk.y);
            unsigned long long hd2 = pack_dup(hk.z), hd3 = pack_dup(hk.w);
            fma2(a[0][0], wA.x, hd0); fma2(a[0][1], wA.y, hd0);
            fma2(a[0][2], wB.x, hd0); fma2(a[0][3], wB.y, hd0);
            fma2(a[1][0], wA.x, hd1); fma2(a[1][1], wA.y, hd1);
            fma2(a[1][2], wB.x, hd1); fma2(a[1][3], wB.y, hd1);
            fma2(a[2][0], wA.x, hd2); fma2(a[2][1], wA.y, hd2);
            fma2(a[2][2], wB.x, hd2); fma2(a[2][3], wB.y, hd2);
            fma2(a[3][0], wA.x, hd3); fma2(a[3][1], wA.y, hd3);
            fma2(a[3][2], wB.x, hd3); fma2(a[3][3], wB.y, hd3);
        }

        __syncwarp();   // all lanes done reading h before overwrite
        #pragma unroll
        for (int r = 0; r < RPW; r++) {
            float i0,i1,f0,f1,g0,g1,o0,o1;
            unpack2(add2(a[r][0], xz0[r].x), i0, i1);
            unpack2(add2(a[r][1], xz0[r].y), f0, f1);
            unpack2(add2(a[r][2], xz1[r].x), g0, g1);
            unpack2(add2(a[r][3], xz1[r].y), o0, o1);
            c0[r] = sigf(f0)*c0[r] + sigf(i0)*tanh_(g0);
            c1[r] = sigf(f1)*c1[r] + sigf(i1)*tanh_(g1);
            hh0[r] = sigf(o0)*tanh_(c0[r]);
            hh1[r] = sigf(o1)*tanh_(c1[r]);
            if (collect) { m0[r] = fmaxf(m0[r], hh0[r]); m1[r] = fmaxf(m1[r], hh1[r]); }
        }
        // two STS.128 instead of 8 conflicted STS.32
        *(float4*)(hs + 8*lane)     = make_float4(hh0[0], hh0[1], hh0[2], hh0[3]);
        *(float4*)(hs + 8*lane + 4) = make_float4(hh1[0], hh1[1], hh1[2], hh1[3]);
        __syncwarp();   // h stores visible before next step's reads
    }

    if (s == 0) {
        #pragma unroll
        for (int r = 0; r < RPW; r++)
            ((float2*)(g_mp + (b0 + r)*HH))[lane] = make_float2(m0[r], m1[r]);
    } else if (s == NSCAN-1) {
        #pragma unroll
        for (int r = 0; r < RPW; r++)
            ((float2*)(g_mf + (b0 + r)*HH))[lane] = make_float2(m0[r], m1[r]);
    } else {
        #pragma unroll
        for (int r = 0; r < RPW; r++)
            ((float2*)(g_hsuf + ((s - 1)*BB + b0 + r)*HH))[lane] =
                make_float2(hh0[r], hh1[r]);
    }
}

// ============================================================================
// Kernel 3: suffix max-reduce + Hs assembly + rank-1 affine epilogue.
// out[b][n][j]      = max(mp,ms)[b][j] * Wlin[n] + blin[n]
// out[b][n][64+j]   = max(ms,mf)[b][j] * Wlin[n] + blin[n]
// ============================================================================
__global__ void __launch_bounds__(256) k_fin(
    const float* __restrict__ Wlin, const float* __restrict__ blin,
    float* __restrict__ out)
{
    int idx = blockIdx.x*blockDim.x + threadIdx.x;   // 0..8191
    int b = idx >> 6, j = idx & 63;
    float ms = -1e30f;
    #pragma unroll
    for (int sc = 0; sc < 25; sc++)
        ms = fmaxf(ms, g_hsuf[(sc*BB + b)*HH + j]);
    float left  = fmaxf(g_mp[b*HH + j], ms);
    float right = fmaxf(ms, g_mf[b*HH + j]);
    #pragma unroll
    for (int n = 0; n < 26; n++) {
        float w = Wlin[n], bl = blin[n];
        out[(b*26 + n)*128 + j]      = fmaf(left,  w, bl);
        out[(b*26 + n)*128 + 64 + j] = fmaf(right, w, bl);
    }
}

// ============================================================================
extern "C" void kernel_launch(void* const* d_in, const int* in_sizes, int n_in,
                              void* d_out, int out_size)
{
    const float* x    = (const float*)d_in[0];
    const float* Wih  = (const float*)d_in[1];
    const float* Whh  = (const float*)d_in[2];
    const float* bih  = (const float*)d_in[3];
    const float* bhh  = (const float*)d_in[4];
    const float* Wlin = (const float*)d_in[5];
    const float* blin = (const float*)d_in[6];
    float* out = (float*)d_out;

    const int smem_bytes = (HH*G4 + WPB*64*RPW) * (int)sizeof(float);  // 70 KB
    cudaFuncSetAttribute(k_xz,  cudaFuncAttributeMaxDynamicSharedMemorySize, smem_bytes);
    cudaFuncSetAttribute(k_rec, cudaFuncAttributeMaxDynamicSharedMemorySize, smem_bytes);

    k_xz <<<512, NTHREADS, smem_bytes>>>(x, Wih, bih, bhh);
    k_rec<<<144, NTHREADS, smem_bytes>>>(Whh);
    k_fin<<<32, 256>>>(Wlin, blin, out);
}

// round 10
// speedup vs baseline: 1.3087x; 1.3087x over previous
#include <cuda_runtime.h>
#include <cstdint>

// Problem constants
#define BB    128    // batch
#define TT    96     // time
#define HH    64     // hidden = input dim
#define G4    256    // 4*H gates
#define NSCAN 27
#define RPW   4      // rows (scan,batch) per warp
#define WPB   6      // warps per block
#define NTHREADS (WPB*32)

// Scratch (static device globals — no allocation)
__device__ __align__(16) float g_xz[BB*TT*G4];     // x@Wih^T + bias, gate-permuted
__device__ __align__(16) float g_hsuf[25*BB*HH];   // final h of suffix scans
__device__ __align__(16) float g_mp[BB*HH];        // running max of forward-prefix h
__device__ __align__(16) float g_mf[BB*HH];        // running max of reverse-prefix h
__device__ __align__(16) float g_wihp[HH*G4];      // pre-permuted Wih
__device__ __align__(16) float g_whhp[HH*G4];      // pre-permuted Whh
__device__ __align__(16) float g_bp[G4];           // pre-permuted bias (bih+bhh)

// SMSP-aware scan assignment (wid%4 -> SMSP; SMSP0:{w0,w4} SMSP1:{w1,w5}
// doubled, SMSP2/3 solo). Solo slots get the 9 longest scans (95..87 steps).
// Doubled SMSPs get fixed pairings with balanced step sums (<=155):
//   (10,0)=111 (11,26)=110 (12,25)=155 (13,24)=155 (14,23)=155
//   (15,22)=155 (16,21)=155 (17,20)=155 (18,19)=155
__constant__ int c_pairA[9] = {10,11,12,13,14,15,16,17,18};
__constant__ int c_pairB[9] = { 0,26,25,24,23,22,21,20,19};

// ---- packed f32x2 helpers (sm_103a) ----
__device__ __forceinline__ unsigned long long pack_dup(float v) {
    unsigned long long r;
    asm("mov.b64 %0, {%1, %1};" : "=l"(r) : "f"(v));
    return r;
}
__device__ __forceinline__ unsigned long long pack2(float lo, float hi) {
    unsigned long long r;
    asm("mov.b64 %0, {%1, %2};" : "=l"(r) : "f"(lo), "f"(hi));
    return r;
}
__device__ __forceinline__ void unpack2(unsigned long long v, float& lo, float& hi) {
    asm("mov.b64 {%0, %1}, %2;" : "=f"(lo), "=f"(hi) : "l"(v));
}
__device__ __forceinline__ void fma2(unsigned long long& acc, unsigned long long a,
                                     unsigned long long b) {
    asm("fma.rn.f32x2 %0, %1, %2, %0;" : "+l"(acc) : "l"(a), "l"(b));
}
__device__ __forceinline__ unsigned long long add2(unsigned long long a, unsigned long long b) {
    unsigned long long r;
    asm("add.rn.f32x2 %0, %1, %2;" : "=l"(r) : "l"(a), "l"(b));
    return r;
}

// ---- activations (~1e-6 rel err, safely under 1e-3 budget) ----
__device__ __forceinline__ float sigf(float x) {
    return __fdividef(1.0f, 1.0f + __expf(-x));
}
__device__ __forceinline__ float tanh_(float x) {
    return __fdividef(2.0f, 1.0f + __expf(-2.0f*x)) - 1.0f;
}

// Permutation (split-half, bank-conflict-free):
// Each 256-float row = [ wA half (128) | wB half (128) ].
//   wA: offset      j*4 + q, q=0..3 -> gate q>>1 (i,f), unit 2j+(q&1)
//   wB: offset 128 + j*4 + q, q=0..3 -> gate 2+(q>>1) (g,o), unit 2j+(q&1)
// Lane j reads 16B at 16B stride per half -> LDS.128 conflict-free.

// ============================================================================
// Kernel 0: one-time gate permutation of weights + bias (coalesced writes).
// Blocks 0..63: Wih row k=blockIdx.  64..127: Whh k=blockIdx-64.  128: bias.
// ============================================================================
__global__ void k_perm(const float* __restrict__ Wih, const float* __restrict__ Whh,
                       const float* __restrict__ bih, const float* __restrict__ bhh)
{
    int c = threadIdx.x;                  // 0..255 = permuted column
    int half = c >> 7, cc = c & 127;
    int j = cc >> 2, q = half*4 + (cc & 3);
    int row = (q >> 1)*64 + 2*j + (q & 1);  // gate*64 + unit
    int b = blockIdx.x;
    if (b < 64) {
        g_wihp[b*G4 + c] = Wih[row*HH + b];
    } else if (b < 128) {
        int k = b - 64;
        g_whhp[k*G4 + c] = Whh[row*HH + k];
    } else {
        g_bp[c] = bih[row] + bhh[row];
    }
}

// ============================================================================
// Kernel 1: XZ[row][col] = bias[col] + sum_k x[row][k] * Wih_perm[k][col]
// grid=128, each block: coalesced 64KB weight copy, then 4 row-groups of
// 24 rows (6 warps x RPW).
// ============================================================================
__global__ void __launch_bounds__(NTHREADS) k_xz(const float* __restrict__ x)
{
    extern __shared__ __align__(16) float smem[];
    float* wsm = smem;                    // [64][256] permuted Wih
    float* xsm = smem + HH*G4;            // [WPB][64][RPW] staged x

    int tid = threadIdx.x;
    // coalesced float4 copy of pre-permuted weights
    {
        const float4* src = (const float4*)g_wihp;
        float4* dst = (float4*)wsm;
        for (int d = tid; d < HH*G4/4; d += NTHREADS) dst[d] = src[d];
    }
    __syncthreads();

    int wid  = tid >> 5, lane = tid & 31;
    float* xs = xsm + wid*(64*RPW);
    const float* wrow = wsm + lane*4;     // 16B lane stride (conflict-free)

    // bias (coalesced float4 from permuted layout)
    float4 bA = *(const float4*)(g_bp + lane*4);
    float4 bB = *(const float4*)(g_bp + 128 + lane*4);
    unsigned long long bp0 = pack2(bA.x, bA.y), bp1 = pack2(bA.z, bA.w);
    unsigned long long bp2 = pack2(bB.x, bB.y), bp3 = pack2(bB.z, bB.w);

    for (int u = 0; u < 4; u++) {
        int row0 = (blockIdx.x*4 + u)*(WPB*RPW) + wid*RPW;

        // stage x rows into [k][r] packed layout
        #pragma unroll
        for (int r = 0; r < RPW; r++) {
            float2 v = ((const float2*)(x + (row0 + r)*HH))[lane];
            xs[(2*lane    )*RPW + r] = v.x;
            xs[(2*lane + 1)*RPW + r] = v.y;
        }
        __syncwarp();

        unsigned long long acc[RPW][4];
        #pragma unroll
        for (int r = 0; r < RPW; r++) {
            acc[r][0] = bp0; acc[r][1] = bp1; acc[r][2] = bp2; acc[r][3] = bp3;
        }

        #pragma unroll 8
        for (int k = 0; k < 64; k++) {
            ulonglong2 wA = *(const ulonglong2*)(wrow + k*G4);
            ulonglong2 wB = *(const ulonglong2*)(wrow + k*G4 + 128);
            float4 xk = *(const float4*)(xs + k*RPW);
            unsigned long long xd0 = pack_dup(xk.x), xd1 = pack_dup(xk.y);
            unsigned long long xd2 = pack_dup(xk.z), xd3 = pack_dup(xk.w);
            fma2(acc[0][0], wA.x, xd0); fma2(acc[0][1], wA.y, xd0);
            fma2(acc[0][2], wB.x, xd0); fma2(acc[0][3], wB.y, xd0);
            fma2(acc[1][0], wA.x, xd1); fma2(acc[1][1], wA.y, xd1);
            fma2(acc[1][2], wB.x, xd1); fma2(acc[1][3], wB.y, xd1);
            fma2(acc[2][0], wA.x, xd2); fma2(acc[2][1], wA.y, xd2);
            fma2(acc[2][2], wB.x, xd2); fma2(acc[2][3], wB.y, xd2);
            fma2(acc[3][0], wA.x, xd3); fma2(acc[3][1], wA.y, xd3);
            fma2(acc[3][2], wB.x, xd3); fma2(acc[3][3], wB.y, xd3);
        }

        #pragma unroll
        for (int r = 0; r < RPW; r++) {
            float* base = g_xz + (row0 + r)*G4;
            *(ulonglong2*)(base + lane*4)       = make_ulonglong2(acc[r][0], acc[r][1]);
            *(ulonglong2*)(base + 128 + lane*4) = make_ulonglong2(acc[r][2], acc[r][3]);
        }
        __syncwarp();   // xs reused next iteration
    }
}

// ============================================================================
// Kernel 2: the 27 LSTM scans. 864 warps, 144 blocks of 6 warps.
// SMSP-aware assignment: solos (wid 2,3) take scans 1..9; doubled SMSPs
// (wid 0&4, 1&5) take balanced scan pairs.
// ============================================================================
__global__ void __launch_bounds__(NTHREADS) k_rec()
{
    extern __shared__ __align__(16) float smem[];
    float* wsm    = smem;                 // [64][256] permuted Whh
    float* hsmall = smem + HH*G4;         // [WPB][64][RPW] h state

    int tid = threadIdx.x;
    {
        const float4* src = (const float4*)g_whhp;
        float4* dst = (float4*)wsm;
        for (int d = tid; d < HH*G4/4; d += NTHREADS) dst[d] = src[d];
    }
    int wid = tid >> 5, lane = tid & 31;
    float* hs = hsmall + wid*(64*RPW);
    #pragma unroll
    for (int i = 0; i < 8; i++) hs[lane + 32*i] = 0.0f;
    __syncthreads();

    // SMSP-aware (scan, batch-group) assignment
    int s, bg;
    if (wid == 2 || wid == 3) {           // solo SMSPs: longest scans
        int slot = blockIdx.x*2 + (wid - 2);   // 0..287 = 9 scans x 32 bg
        s  = 1 + slot % 9;                     // scans 1..9 (95..87 steps)
        bg = slot / 9;
    } else {                              // doubled SMSPs: balanced pairs
        int p   = blockIdx.x*2 + (wid & 1);    // pair slot 0..287 = 9 x 32
        int pid = p % 9;
        bg = p / 9;
        s  = (wid < 4) ? c_pairA[pid] : c_pairB[pid];
    }
    int b0 = bg * RPW;

    int tt, tstep, nsteps;
    if (s == 0)            { tt = 0;  tstep = 1;  nsteps = 25; }
    else if (s == NSCAN-1) { tt = 95; tstep = -1; nsteps = 25; }
    else                   { tt = s;  tstep = 1;  nsteps = 96 - s; }
    const bool collect = (s == 0) || (s == NSCAN-1);

    float c0[RPW], c1[RPW], m0[RPW], m1[RPW], hh0[RPW], hh1[RPW];
    #pragma unroll
    for (int r = 0; r < RPW; r++) {
        c0[r] = c1[r] = 0.0f; hh0[r] = hh1[r] = 0.0f;
        m0[r] = m1[r] = -1e30f;
    }

    const float* wrow = wsm + lane*4;     // 16B lane stride (conflict-free)

    for (int step = 0; step < nsteps; step++, tt += tstep) {
        // prefetch XZ (L2-resident) — consumed after the k-loop
        ulonglong2 xz0[RPW], xz1[RPW];
        #pragma unroll
        for (int r = 0; r < RPW; r++) {
            const float* base = g_xz + ((b0 + r)*TT + tt)*G4;
            xz0[r] = *(const ulonglong2*)(base + lane*4);
            xz1[r] = *(const ulonglong2*)(base + 128 + lane*4);
        }

        unsigned long long a[RPW][4];
        #pragma unroll
        for (int r = 0; r < RPW; r++)
            a[r][0] = a[r][1] = a[r][2] = a[r][3] = 0ull;

        #pragma unroll 8
        for (int k = 0; k < 64; k++) {
            ulonglong2 wA = *(const ulonglong2*)(wrow + k*G4);
            ulonglong2 wB = *(const ulonglong2*)(wrow + k*G4 + 128);
            float4 hk = *(const float4*)(hs + k*RPW);   // broadcast, conflict-free
            unsigned long long hd0 = pack_dup(hk.x), hd1 = pack_dup(hk.y);
            unsigned long long hd2 = pack_dup(hk.z), hd3 = pack_dup(hk.w);
            fma2(a[0][0], wA.x, hd0); fma2(a[0][1], wA.y, hd0);
            fma2(a[0][2], wB.x, hd0); fma2(a[0][3], wB.y, hd0);
            fma2(a[1][0], wA.x, hd1); fma2(a[1][1], wA.y, hd1);
            fma2(a[1][2], wB.x, hd1); fma2(a[1][3], wB.y, hd1);
            fma2(a[2][0], wA.x, hd2); fma2(a[2][1], wA.y, hd2);
            fma2(a[2][2], wB.x, hd2); fma2(a[2][3], wB.y, hd2);
            fma2(a[3][0], wA.x, hd3); fma2(a[3][1], wA.y, hd3);
            fma2(a[3][2], wB.x, hd3); fma2(a[3][3], wB.y, hd3);
        }

        __syncwarp();   // all lanes done reading h before overwrite
        #pragma unroll
        for (int r = 0; r < RPW; r++) {
            float i0,i1,f0,f1,g0,g1,o0,o1;
            unpack2(add2(a[r][0], xz0[r].x), i0, i1);
            unpack2(add2(a[r][1], xz0[r].y), f0, f1);
            unpack2(add2(a[r][2], xz1[r].x), g0, g1);
            unpack2(add2(a[r][3], xz1[r].y), o0, o1);
            c0[r] = sigf(f0)*c0[r] + sigf(i0)*tanh_(g0);
            c1[r] = sigf(f1)*c1[r] + sigf(i1)*tanh_(g1);
            hh0[r] = sigf(o0)*tanh_(c0[r]);
            hh1[r] = sigf(o1)*tanh_(c1[r]);
            if (collect) { m0[r] = fmaxf(m0[r], hh0[r]); m1[r] = fmaxf(m1[r], hh1[r]); }
        }
        // two STS.128 (conflict-free) instead of 8 scattered STS.32
        *(float4*)(hs + 8*lane)     = make_float4(hh0[0], hh0[1], hh0[2], hh0[3]);
        *(float4*)(hs + 8*lane + 4) = make_float4(hh1[0], hh1[1], hh1[2], hh1[3]);
        __syncwarp();   // h stores visible before next step's reads
    }

    if (s == 0) {
        #pragma unroll
        for (int r = 0; r < RPW; r++)
            ((float2*)(g_mp + (b0 + r)*HH))[lane] = make_float2(m0[r], m1[r]);
    } else if (s == NSCAN-1) {
        #pragma unroll
        for (int r = 0; r < RPW; r++)
            ((float2*)(g_mf + (b0 + r)*HH))[lane] = make_float2(m0[r], m1[r]);
    } else {
        #pragma unroll
        for (int r = 0; r < RPW; r++)
            ((float2*)(g_hsuf + ((s - 1)*BB + b0 + r)*HH))[lane] =
                make_float2(hh0[r], hh1[r]);
    }
}

// ============================================================================
// Kernel 3: suffix max-reduce + Hs assembly + rank-1 affine epilogue.
// ============================================================================
__global__ void __launch_bounds__(256) k_fin(
    const float* __restrict__ Wlin, const float* __restrict__ blin,
    float* __restrict__ out)
{
    int idx = blockIdx.x*blockDim.x + threadIdx.x;   // 0..8191
    int b = idx >> 6, j = idx & 63;
    float ms = -1e30f;
    #pragma unroll
    for (int sc = 0; sc < 25; sc++)
        ms = fmaxf(ms, g_hsuf[(sc*BB + b)*HH + j]);
    float left  = fmaxf(g_mp[b*HH + j], ms);
    float right = fmaxf(ms, g_mf[b*HH + j]);
    #pragma unroll
    for (int n = 0; n < 26; n++) {
        float w = Wlin[n], bl = blin[n];
        out[(b*26 + n)*128 + j]      = fmaf(left,  w, bl);
        out[(b*26 + n)*128 + 64 + j] = fmaf(right, w, bl);
    }
}

// ============================================================================
extern "C" void kernel_launch(void* const* d_in, const int* in_sizes, int n_in,
                              void* d_out, int out_size)
{
    const float* x    = (const float*)d_in[0];
    const float* Wih  = (const float*)d_in[1];
    const float* Whh  = (const float*)d_in[2];
    const float* bih  = (const float*)d_in[3];
    const float* bhh  = (const float*)d_in[4];
    const float* Wlin = (const float*)d_in[5];
    const float* blin = (const float*)d_in[6];
    float* out = (float*)d_out;

    const int smem_bytes = (HH*G4 + WPB*64*RPW) * (int)sizeof(float);  // 70 KB
    cudaFuncSetAttribute(k_xz,  cudaFuncAttributeMaxDynamicSharedMemorySize, smem_bytes);
    cudaFuncSetAttribute(k_rec, cudaFuncAttributeMaxDynamicSharedMemorySize, smem_bytes);

    k_perm<<<129, 256>>>(Wih, Whh, bih, bhh);
    k_xz <<<128, NTHREADS, smem_bytes>>>(x);
    k_rec<<<144, NTHREADS, smem_bytes>>>();
    k_fin<<<32, 256>>>(Wlin, blin, out);
}